// round 8
// baseline (speedup 1.0000x reference)
#include <cuda_runtime.h>

// InfoEnlargeEmbedding: out[b,l,:] = concat(x[b,l,:], x[b,idxs[b,0],:], x[b,idxs[b,1],:])
// B=64, L=1024, D=256, K=2.
// R8: R6 structure re-expressed in 256-bit (double4) accesses — halves the
// request count through L1TEX/LTS for the same bytes. 96 threads/block:
// 32 copy lanes (2 chunks x 4 rows of LDG.256->STG.256), 64 gather lanes
// (1 L2-hit LDG.256 -> 8 STG.256).

static constexpr int B = 64;
static constexpr int L = 1024;
static constexpr int D8 = 32;               // 32-byte words per source row (256 floats)
static constexpr int K = 2;
static constexpr int OUT8 = D8 * (1 + K);   // 96 words per output row
static constexpr int R = 8;                 // rows per block
static constexpr int H = 4;                 // copy pipeline chunk (rows)
static constexpr int T = 96;

__global__ void __launch_bounds__(T)
info_enlarge_kernel(const double4* __restrict__ x,
                    const int* __restrict__ idxs,
                    double4* __restrict__ out) {
    const int row0 = blockIdx.x * R;        // base bl; all R rows share b
    const int b    = row0 >> 10;            // / L
    const int c    = threadIdx.x;           // 0..95

    if (c < D8) {
        // Straight copy: two chunks of 4 independent 256-bit load->store.
        #pragma unroll
        for (int h = 0; h < R / H; h++) {
            const int rb = row0 + h * H;
            double4 v[H];
            #pragma unroll
            for (int u = 0; u < H; u++)
                v[u] = x[(size_t)(rb + u) * D8 + c];
            #pragma unroll
            for (int u = 0; u < H; u++)
                out[(size_t)(rb + u) * OUT8 + c] = v[u];
        }
    } else {
        // Gather: one 256-bit L2-hit load, broadcast-stored to 8 rows.
        const int kd = c - D8;              // 0..63
        const int k  = kd >> 5;             // / D8
        const int dd = kd & (D8 - 1);
        const int li = __ldg(idxs + b * K + k);
        const double4 v = x[((size_t)b * L + li) * D8 + dd];
        #pragma unroll
        for (int u = 0; u < R; u++)
            out[(size_t)(row0 + u) * OUT8 + c] = v;
    }
}

extern "C" void kernel_launch(void* const* d_in, const int* in_sizes, int n_in,
                              void* d_out, int out_size) {
    const double4* x = (const double4*)d_in[0];
    const int* idxs  = (const int*)d_in[1];
    double4* out     = (double4*)d_out;

    info_enlarge_kernel<<<(B * L) / R, T>>>(x, idxs, out);
}

// round 9
// speedup vs baseline: 1.2069x; 1.2069x over previous
#include <cuda_runtime.h>

// InfoEnlargeEmbedding: out[b,l,:] = concat(x[b,l,:], x[b,idxs[b,0],:], x[b,idxs[b,1],:])
// B=64, L=1024, D=256, K=2.
// R9: persistent grid-stride version of R6 (best: 40.2us). One wave of
// 148x8 CTAs; each walks ~7 tiles of 8 rows. Removes wave-transition/tail
// overhead and keeps load/store streams continuous across iterations.

static constexpr int B = 64;
static constexpr int L = 1024;
static constexpr int D4 = 64;               // float4 per source row
static constexpr int K = 2;
static constexpr int OUT4 = D4 * (1 + K);   // 192 float4 per output row
static constexpr int R = 8;                 // rows per tile
static constexpr int NTILES = (B * L) / R;  // 8192
static constexpr int NSM = 148;
static constexpr int CTAS = NSM * 8;        // 1184, single wave

__global__ void __launch_bounds__(OUT4)
info_enlarge_kernel(const float4* __restrict__ x,
                    const int* __restrict__ idxs,
                    float4* __restrict__ out) {
    const int c = threadIdx.x;              // 0..191

    for (int tile = blockIdx.x; tile < NTILES; tile += CTAS) {
        const int row0 = tile * R;          // base bl; all R rows share b
        const int b    = row0 >> 10;        // / L

        if (c < D4) {
            // Straight copy: 8 independent loads, then 8 stores.
            float4 v[R];
            #pragma unroll
            for (int u = 0; u < R; u++)
                v[u] = x[(size_t)(row0 + u) * D4 + c];
            #pragma unroll
            for (int u = 0; u < R; u++)
                out[(size_t)(row0 + u) * OUT4 + c] = v[u];
        } else {
            // Gather: one L2-hit load broadcast-stored to 8 rows.
            const int kd = c - D4;
            const int k  = kd >> 6;         // / D4
            const int dd = kd & (D4 - 1);
            const int li = __ldg(idxs + b * K + k);
            const float4 v = __ldg(x + ((size_t)b * L + li) * D4 + dd);
            #pragma unroll
            for (int u = 0; u < R; u++)
                out[(size_t)(row0 + u) * OUT4 + c] = v;
        }
    }
}

extern "C" void kernel_launch(void* const* d_in, const int* in_sizes, int n_in,
                              void* d_out, int out_size) {
    const float4* x  = (const float4*)d_in[0];
    const int* idxs  = (const int*)d_in[1];
    float4* out      = (float4*)d_out;

    info_enlarge_kernel<<<CTAS, OUT4>>>(x, idxs, out);
}

// round 10
// speedup vs baseline: 1.3485x; 1.1173x over previous
#include <cuda_runtime.h>

// InfoEnlargeEmbedding: out[b,l,:] = concat(x[b,l,:], x[b,idxs[b,0],:], x[b,idxs[b,1],:])
// B=64, L=1024, D=256, K=2.
// R10: exact R6 structure (best: 40.16us kernel) with WRITE-THROUGH stores
// (__stwt): output never allocates dirty lines in L2, eliminating the
// victim-writeback drain path and keeping x fully L2-resident.

static constexpr int B = 64;
static constexpr int L = 1024;
static constexpr int D4 = 64;               // float4 per source row
static constexpr int K = 2;
static constexpr int OUT4 = D4 * (1 + K);   // 192 float4 per output row
static constexpr int R = 8;                 // rows (bl) per block

__global__ void __launch_bounds__(OUT4)
info_enlarge_kernel(const float4* __restrict__ x,
                    const int* __restrict__ idxs,
                    float4* __restrict__ out) {
    const int row0 = blockIdx.x * R;        // base bl; all R rows share b
    const int b    = row0 >> 10;            // / L
    const int c    = threadIdx.x;           // 0..191

    if (c < D4) {
        // Straight copy region: 8 independent loads, then 8 write-through stores.
        float4 v[R];
        #pragma unroll
        for (int u = 0; u < R; u++)
            v[u] = x[(size_t)(row0 + u) * D4 + c];
        #pragma unroll
        for (int u = 0; u < R; u++)
            __stwt(out + (size_t)(row0 + u) * OUT4 + c, v[u]);
    } else {
        // Gather region: one L2-hit load, broadcast to 8 rows.
        const int kd = c - D4;
        const int k  = kd >> 6;             // / D4
        const int dd = kd & (D4 - 1);
        const int li = __ldg(idxs + b * K + k);
        const float4 v = __ldg(x + ((size_t)b * L + li) * D4 + dd);
        #pragma unroll
        for (int u = 0; u < R; u++)
            __stwt(out + (size_t)(row0 + u) * OUT4 + c, v);
    }
}

extern "C" void kernel_launch(void* const* d_in, const int* in_sizes, int n_in,
                              void* d_out, int out_size) {
    const float4* x  = (const float4*)d_in[0];
    const int* idxs  = (const int*)d_in[1];
    float4* out      = (float4*)d_out;

    info_enlarge_kernel<<<(B * L) / R, OUT4>>>(x, idxs, out);
}